// round 7
// baseline (speedup 1.0000x reference)
#include <cuda_runtime.h>
#include <cuda_bf16.h>
#include <cstdint>

#define BM 128
#define BN 128
#define NST 128             // stages; 8 input features per stage
#define SLOTS 72            // K-slots per stage (8 features x 9, no pad)
#define ROWB 176            // padded SMEM row stride bytes (conflict-free LDSM)
#define PLB (128*ROWB)      // 22528 per plane
#define BUFB (4*PLB)        // Ah, Al, Bh, Bl
#define SMEM_TOT (2*BUFB)   // 180224
#define NTHR 512

// pre-expanded operands, stage-major bf16 hi/lo planes
__device__ __align__(16) __nv_bfloat16 g_ah[(size_t)NST * 8192 * SLOTS];
__device__ __align__(16) __nv_bfloat16 g_al[(size_t)NST * 8192 * SLOTS];
__device__ __align__(16) __nv_bfloat16 g_bh[(size_t)NST * 1024 * SLOTS];
__device__ __align__(16) __nv_bfloat16 g_bl[(size_t)NST * 1024 * SLOTS];

static __device__ __forceinline__ uint32_t s2u(const void* p) {
    uint32_t a;
    asm("{ .reg .u64 t; cvta.to.shared.u64 t, %1; cvt.u32.u64 %0, t; }" : "=r"(a) : "l"(p));
    return a;
}
static __device__ __forceinline__ void cp16(uint32_t dst, const void* src) {
    asm volatile("cp.async.cg.shared.global [%0], [%1], 16;" :: "r"(dst), "l"(src));
}
static __device__ __forceinline__ void ldm4(uint32_t* r, uint32_t addr) {
    asm volatile("ldmatrix.sync.aligned.m8n8.x4.shared.b16 {%0,%1,%2,%3}, [%4];"
                 : "=r"(r[0]), "=r"(r[1]), "=r"(r[2]), "=r"(r[3]) : "r"(addr));
}
static __device__ __forceinline__ void mma16(float* c, const uint32_t* a,
                                             uint32_t b0, uint32_t b1) {
    asm volatile("mma.sync.aligned.m16n8k16.row.col.f32.bf16.bf16.f32 "
                 "{%0,%1,%2,%3}, {%4,%5,%6,%7}, {%8,%9}, {%0,%1,%2,%3};"
                 : "+f"(c[0]), "+f"(c[1]), "+f"(c[2]), "+f"(c[3])
                 : "r"(a[0]), "r"(a[1]), "r"(a[2]), "r"(a[3]), "r"(b0), "r"(b1));
}
static __device__ __forceinline__ void mma8(float* c, uint32_t a0, uint32_t a1, uint32_t b0) {
    asm volatile("mma.sync.aligned.m16n8k8.row.col.f32.bf16.bf16.f32 "
                 "{%0,%1,%2,%3}, {%4,%5}, {%6}, {%0,%1,%2,%3};"
                 : "+f"(c[0]), "+f"(c[1]), "+f"(c[2]), "+f"(c[3])
                 : "r"(a0), "r"(a1), "r"(b0));
}

// ---------------- prep: expand + hi/lo split x into A planes ----------------
__global__ void xexp_kernel(const float* __restrict__ x, const float* __restrict__ gr) {
    __shared__ float s_kn[12], s_rL[30], s_rR[30];
    const int tid = threadIdx.x;
    if (tid < 12) s_kn[tid] = gr[tid];
    __syncthreads();
    if (tid < 30) {
        int p = tid / 10 + 1, j = tid % 10;
        if (j <= 10 - p) {
            s_rL[tid] = 1.f / (s_kn[j + p] - s_kn[j]);
            s_rR[tid] = 1.f / (s_kn[j + p + 1] - s_kn[j + 1]);
        } else { s_rL[tid] = 0.f; s_rR[tid] = 0.f; }
    }
    __syncthreads();

    const int s   = blockIdx.y;                       // stage
    const int row = blockIdx.x * 256 + tid;           // batch row
    float4 x0 = *(const float4*)(x + (size_t)row * 1024 + s * 8);
    float4 x1 = *(const float4*)(x + (size_t)row * 1024 + s * 8 + 4);
    float xs[8] = {x0.x, x0.y, x0.z, x0.w, x1.x, x1.y, x1.z, x1.w};

    __nv_bfloat16 hi[SLOTS], lo[SLOTS];
#pragma unroll
    for (int f = 0; f < 8; f++) {
        float v0 = xs[f];
        float b[11];
#pragma unroll
        for (int j = 0; j < 11; j++) b[j] = (v0 >= s_kn[j] && v0 < s_kn[j + 1]) ? 1.f : 0.f;
#pragma unroll
        for (int p = 1; p <= 3; p++)
#pragma unroll
            for (int j = 0; j <= 10 - p; j++)
                b[j] = (v0 - s_kn[j]) * s_rL[(p - 1) * 10 + j] * b[j]
                     + (s_kn[j + p + 1] - v0) * s_rR[(p - 1) * 10 + j] * b[j + 1];
        float v[9];
        v[0] = v0;
#pragma unroll
        for (int c = 0; c < 8; c++) v[1 + c] = b[c];
#pragma unroll
        for (int j = 0; j < 9; j++) {
            __nv_bfloat16 h = __float2bfloat16(v[j]);
            hi[f * 9 + j] = h;
            lo[f * 9 + j] = __float2bfloat16(v[j] - __bfloat162float(h));
        }
    }
    uint4* dh = (uint4*)(g_ah + ((size_t)s * 8192 + row) * SLOTS);
    uint4* dl = (uint4*)(g_al + ((size_t)s * 8192 + row) * SLOTS);
#pragma unroll
    for (int j = 0; j < 9; j++) { dh[j] = ((uint4*)hi)[j]; dl[j] = ((uint4*)lo)[j]; }
}

// ---------------- prep: expand + hi/lo split weights ----------------
__global__ void wexp_kernel(const float* __restrict__ bw, const float* __restrict__ sw) {
    int n = blockIdx.x;      // output feature
    int s = threadIdx.x;     // stage
    __nv_bfloat16 hi[SLOTS], lo[SLOTS];
    const float* bwr = bw + (size_t)n * 1024 + s * 8;
    const float* swr = sw + ((size_t)n * 1024 + (size_t)s * 8) * 8;
#pragma unroll
    for (int f = 0; f < 8; f++) {
        float v[9];
        v[0] = bwr[f];
#pragma unroll
        for (int j = 0; j < 8; j++) v[1 + j] = swr[f * 8 + j];
#pragma unroll
        for (int j = 0; j < 9; j++) {
            __nv_bfloat16 h = __float2bfloat16(v[j]);
            hi[f * 9 + j] = h;
            lo[f * 9 + j] = __float2bfloat16(v[j] - __bfloat162float(h));
        }
    }
    uint4* dh = (uint4*)(g_bh + ((size_t)s * 1024 + n) * SLOTS);
    uint4* dl = (uint4*)(g_bl + ((size_t)s * 1024 + n) * SLOTS);
#pragma unroll
    for (int j = 0; j < 9; j++) { dh[j] = ((uint4*)hi)[j]; dl[j] = ((uint4*)lo)[j]; }
}

// ---------------- main pure GEMM ----------------
__global__ __launch_bounds__(NTHR, 1)
void kan_mma(float* __restrict__ out) {
    extern __shared__ char smem[];
    const int tid  = threadIdx.x;
    const int lane = tid & 31, wid = tid >> 5;
    const int on0  = blockIdx.x * BN, bm0 = blockIdx.y * BM;
    const uint32_t sb = s2u(smem);

    // copy roles: 4 planes x 128 rows, 9 cp16 per thread per stage
    const int crow = tid & 127, role = tid >> 7;   // 0=Ah 1=Al 2=Bh 3=Bl
    const __nv_bfloat16* gsrc =
        (role == 0 ? g_ah : role == 1 ? g_al : role == 2 ? g_bh : g_bl)
        + (size_t)((role < 2 ? bm0 : on0) + crow) * SLOTS;
    const size_t sstr = (size_t)(role < 2 ? 8192 : 1024) * SLOTS;
    const uint32_t cdst = sb + role * PLB + crow * ROWB;

    // compute roles: 4x4 warps, 32x32 tile each
    const int wm = wid & 3, wn = wid >> 2;
    const int g = lane >> 2, t = lane & 3;

    // ldmatrix per-lane offsets (k16 path)
    const uint32_t a_off = (uint32_t)((((lane >> 3) & 1) * 8 + (lane & 7)) * ROWB + (lane >> 4) * 16);
    const uint32_t b_off = (uint32_t)(((lane >> 4) * 8 + (lane & 7)) * ROWB + ((lane >> 3) & 1) * 16);
    const uint32_t k8_off = (uint32_t)(lane * ROWB + 128);   // slots 64-71

    float acc[2][4][4];
#pragma unroll
    for (int mt = 0; mt < 2; mt++)
#pragma unroll
        for (int nt = 0; nt < 4; nt++)
#pragma unroll
            for (int r = 0; r < 4; r++) acc[mt][nt][r] = 0.f;

    auto issue = [&](int s, int buf) {
        const __nv_bfloat16* src = gsrc + (size_t)s * sstr;
        uint32_t d = cdst + buf * BUFB;
#pragma unroll
        for (int j = 0; j < 9; j++) cp16(d + j * 16, src + j * 8);
        asm volatile("cp.async.commit_group;" ::: "memory");
    };

    issue(0, 0);
    asm volatile("cp.async.wait_group 0;" ::: "memory");
    __syncthreads();

    for (int s = 0; s < NST; ++s) {
        const int buf = s & 1;
        if (s + 1 < NST) issue(s + 1, buf ^ 1);

        const uint32_t bo  = sb + buf * BUFB;
        const uint32_t Ahb = bo + wm * 32 * ROWB;
        const uint32_t Alb = Ahb + PLB;
        const uint32_t Bhb = bo + 2 * PLB + wn * 32 * ROWB;
        const uint32_t Blb = Bhb + PLB;

#pragma unroll
        for (int kk = 0; kk < 4; kk++) {
            const uint32_t kb = kk * 32;
            uint32_t ah[2][4], al[2][4], bh[8], bl[8];
            ldm4(ah[0], Ahb + a_off + kb);
            ldm4(ah[1], Ahb + 16 * ROWB + a_off + kb);
            ldm4(al[0], Alb + a_off + kb);
            ldm4(al[1], Alb + 16 * ROWB + a_off + kb);
            ldm4(bh,     Bhb + b_off + kb);
            ldm4(bh + 4, Bhb + 16 * ROWB + b_off + kb);
            ldm4(bl,     Blb + b_off + kb);
            ldm4(bl + 4, Blb + 16 * ROWB + b_off + kb);
            // term-major ordering: spaces dependent MMAs 8 apart
#pragma unroll
            for (int mt = 0; mt < 2; mt++)
#pragma unroll
                for (int nt = 0; nt < 4; nt++)
                    mma16(acc[mt][nt], ah[mt], bh[2 * nt], bh[2 * nt + 1]);
#pragma unroll
            for (int mt = 0; mt < 2; mt++)
#pragma unroll
                for (int nt = 0; nt < 4; nt++)
                    mma16(acc[mt][nt], ah[mt], bl[2 * nt], bl[2 * nt + 1]);
#pragma unroll
            for (int mt = 0; mt < 2; mt++)
#pragma unroll
                for (int nt = 0; nt < 4; nt++)
                    mma16(acc[mt][nt], al[mt], bh[2 * nt], bh[2 * nt + 1]);
        }
        // k8 tail: slots 64-71
        {
            uint32_t a8h[4], a8l[4], b8h[4], b8l[4];
            ldm4(a8h, Ahb + k8_off);
            ldm4(a8l, Alb + k8_off);
            ldm4(b8h, Bhb + k8_off);
            ldm4(b8l, Blb + k8_off);
#pragma unroll
            for (int mt = 0; mt < 2; mt++)
#pragma unroll
                for (int nt = 0; nt < 4; nt++)
                    mma8(acc[mt][nt], a8h[2 * mt], a8h[2 * mt + 1], b8h[nt]);
#pragma unroll
            for (int mt = 0; mt < 2; mt++)
#pragma unroll
                for (int nt = 0; nt < 4; nt++)
                    mma8(acc[mt][nt], a8h[2 * mt], a8h[2 * mt + 1], b8l[nt]);
#pragma unroll
            for (int mt = 0; mt < 2; mt++)
#pragma unroll
                for (int nt = 0; nt < 4; nt++)
                    mma8(acc[mt][nt], a8l[2 * mt], a8l[2 * mt + 1], b8h[nt]);
        }
        asm volatile("cp.async.wait_group 0;" ::: "memory");
        __syncthreads();
    }

    // ---- epilogue ----
#pragma unroll
    for (int mt = 0; mt < 2; mt++) {
#pragma unroll
        for (int nt = 0; nt < 4; nt++) {
            int r = bm0 + wm * 32 + mt * 16 + g;
            int c = on0 + wn * 32 + nt * 8 + 2 * t;
            *(float2*)(out + (size_t)r * 1024 + c)       = make_float2(acc[mt][nt][0], acc[mt][nt][1]);
            *(float2*)(out + (size_t)(r + 8) * 1024 + c) = make_float2(acc[mt][nt][2], acc[mt][nt][3]);
        }
    }
}

extern "C" void kernel_launch(void* const* d_in, const int* in_sizes, int n_in,
                              void* d_out, int out_size) {
    const float* x  = (const float*)d_in[0];   // (8192, 1024)
    const float* bw = (const float*)d_in[1];   // (1024, 1024)
    const float* sw = (const float*)d_in[2];   // (1024, 1024, 8)
    const float* gr = (const float*)d_in[3];   // (1024, 12)
    float* out = (float*)d_out;                // (8192, 1024)

    cudaFuncSetAttribute(kan_mma, cudaFuncAttributeMaxDynamicSharedMemorySize, SMEM_TOT);
    xexp_kernel<<<dim3(8192 / 256, NST), 256>>>(x, gr);
    wexp_kernel<<<1024, NST>>>(bw, sw);
    kan_mma<<<dim3(8, 64), NTHR, SMEM_TOT>>>(out);
}